// round 14
// baseline (speedup 1.0000x reference)
#include <cuda_runtime.h>
#include <math.h>

#define Bc 2
#define Hc 1080
#define Wc 1920
#define Kc 2048
#define Pc 256
#define PITCH 68   // 68 mod 32 = 4: row-walks (stride 1) and column-walks
                   // (stride 68) both conflict-free; 68 mod 4 = 0 keeps
                   // float4 STS 16B-aligned. Zero swizzle ALU.

__global__ __launch_bounds__(256, 6)
void brief_desc_kernel(const float* __restrict__ img,
                       const float* __restrict__ kp,
                       const float* __restrict__ ori,
                       const float* __restrict__ oy1v,
                       const float* __restrict__ ox1v,
                       const float* __restrict__ oy2v,
                       const float* __restrict__ ox2v,
                       const float* __restrict__ thr,
                       const int*   __restrict__ radii,
                       float* __restrict__ out)
{
    __shared__ float S[64 * PITCH];  // 17.4 KB linear SAT
    __shared__ float seg[64 * 5];    // column-scan segment totals, stride 5
    __shared__ float red[8];

    const int blk = blockIdx.x;      // b*K + k
    const int b   = blk >> 11;       // Kc = 2048
    const int tid = threadIdx.x;

    // --- minimal pre-phase state: patch origin only (keeps regs low in A/B) ---
    int iy, ix;
    {
        const float kpy = kp[blk * 2 + 0];
        const float kpx = kp[blk * 2 + 1];
        iy = (int)rintf(fminf(fmaxf(kpy, 0.0f), (float)(Hc - 1)));
        ix = (int)rintf(fminf(fmaxf(kpx, 0.0f), (float)(Wc - 1)));
    }
    const int oy0 = iy - 31;
    const int ox0 = (ix - 31) & ~3;  // 4-aligned for float4 LDG
    const float* imb = img + (size_t)b * Hc * Wc;

    // ===== Phase A: fused load + row prefix (coalesced float4 + shfl scan) =====
    {
        const int lane16 = tid & 15;          // chunk index within row
        const int grp    = tid >> 4;          // 16 row-groups; warp = 2 rows
        const int gxc    = ox0 + (lane16 << 2);
        const bool xok   = (gxc >= 0) & (gxc <= Wc - 4);  // chunks never straddle

        #pragma unroll
        for (int p = 0; p < 4; p++) {
            const int r  = (p << 4) + grp;
            const int gy = oy0 + r;
            float4 e = make_float4(0.f, 0.f, 0.f, 0.f);
            if (xok && gy >= 0 && gy < Hc)
                e = *reinterpret_cast<const float4*>(imb + (size_t)gy * Wc + gxc);

            float v0 = e.x;
            float v1 = v0 + e.y;
            float v2 = v1 + e.z;
            float v3 = v2 + e.w;

            float t = v3;                     // inclusive scan of chunk totals
            #pragma unroll
            for (int d = 1; d < 16; d <<= 1) {
                const float n = __shfl_up_sync(0xffffffffu, t, d, 16);
                if (lane16 >= d) t += n;
            }
            const float off = t - v3;         // exclusive prefix for this chunk

            *reinterpret_cast<float4*>(&S[r * PITCH + (lane16 << 2)]) =
                make_float4(v0 + off, v1 + off, v2 + off, v3 + off);
        }
    }
    __syncthreads();

    // ===== Phase B: column prefix, parallel over 4 segments of 16 rows =====
    // v[16] register-buffered scan; linear stride-PITCH walk (immediate offsets).
    {
        const int c    = tid & 63;            // column
        const int q    = tid >> 6;            // row segment 0..3
        const int base = (q << 4) * PITCH + c;

        float v[16];
        float s = 0.0f;
        #pragma unroll
        for (int i = 0; i < 16; i++) {
            s += S[base + i * PITCH];
            v[i] = s;
        }
        seg[c * 5 + q] = s;
        __syncthreads();

        float off = 0.0f;
        #pragma unroll
        for (int qq = 0; qq < 3; qq++)
            if (qq < q) off += seg[c * 5 + qq];

        #pragma unroll
        for (int i = 0; i < 16; i++)
            S[base + i * PITCH] = v[i] + off;
    }
    __syncthreads();

    // ===== Phase C: deferred keypoint/pattern state + sampling =====
    const float kpy = kp[blk * 2 + 0];        // broadcast reload (L1-hit)
    const float kpx = kp[blk * 2 + 1];
    const float valid = (kpy >= 0.0f) ? 1.0f : 0.0f;
    const float y = fminf(fmaxf(kpy, 0.0f), (float)(Hc - 1));
    const float x = fminf(fmaxf(kpx, 0.0f), (float)(Wc - 1));

    const float theta = ori[(size_t)b * Hc * Wc + (size_t)iy * Wc + ix];
    float st, ct;
    sincosf(theta, &st, &ct);

    const float o_y1 = oy1v[tid];
    const float o_x1 = ox1v[tid];
    const float o_y2 = oy2v[tid];
    const float o_x2 = ox2v[tid];
    const float th   = thr[tid];
    const int   rad  = radii[tid];
    const float dn   = (float)(2 * rad + 1);
    const float invden = 1.0f / (dn * dn);

    const float p1y = y + (o_x1 * st + o_y1 * ct);
    const float p1x = x + (o_x1 * ct - o_y1 * st);
    const float p2y = y + (o_x2 * st + o_y2 * ct);
    const float p2x = x + (o_x2 * ct - o_y2 * st);

    auto boxavg = [&](float py, float px) -> float {
        // reference order: round first, then clip
        const float jyf = fminf(fmaxf(rintf(py), 0.0f), (float)(Hc - 1));
        const float jxf = fminf(fmaxf(rintf(px), 0.0f), (float)(Wc - 1));
        const int ly = (int)jyf - oy0;        // in [8,54]
        const int lx = (int)jxf - ox0;        // in [8,57]
        const int y1 = (ly - rad - 1) * PITCH, y2 = (ly + rad) * PITCH;
        const int x1 = lx - rad - 1,           x2 = lx + rad;
        const float s = S[y2 + x2] - S[y1 + x2] - S[y2 + x1] + S[y1 + x1];
        return s * invden;
    };

    const float d = boxavg(p1y, p1x) - boxavg(p2y, p2x) - th;

    // ===== Phase D: L2 normalize + write =====
    float sq = d * d;
    #pragma unroll
    for (int off = 16; off; off >>= 1)
        sq += __shfl_xor_sync(0xffffffffu, sq, off);
    if ((tid & 31) == 0) red[tid >> 5] = sq;
    __syncthreads();
    const float tot = red[0] + red[1] + red[2] + red[3]
                    + red[4] + red[5] + red[6] + red[7];
    const float norm  = sqrtf(tot);
    const float scale = valid / fmaxf(norm, 1e-12f);

    out[(size_t)blk * Pc + tid] = d * scale;
}

extern "C" void kernel_launch(void* const* d_in, const int* in_sizes, int n_in,
                              void* d_out, int out_size)
{
    const float* img  = (const float*)d_in[0];  // image (B,1,H,W)
    const float* kp   = (const float*)d_in[1];  // keypoints (B,K,2)
    const float* ori  = (const float*)d_in[2];  // orientation (B,1,H,W)
    const float* oy1  = (const float*)d_in[3];
    const float* ox1  = (const float*)d_in[4];
    const float* oy2  = (const float*)d_in[5];
    const float* ox2  = (const float*)d_in[6];
    const float* thr  = (const float*)d_in[7];
    const int*   rad  = (const int*)d_in[8];
    float* out = (float*)d_out;

    brief_desc_kernel<<<Bc * Kc, Pc>>>(img, kp, ori, oy1, ox1, oy2, ox2, thr, rad, out);
}

// round 15
// speedup vs baseline: 1.0168x; 1.0168x over previous
#include <cuda_runtime.h>
#include <math.h>

#define Bc 2
#define Hc 1080
#define Wc 1920
#define Kc 2048
#define Pc 256
#define NR 60      // rows needed: [iy-30, iy+29]
#define PITCH 68   // 68 mod 32 = 4: row-walks and column-walks conflict-free;
                   // 68 mod 4 = 0 keeps float4 STS 16B-aligned. No swizzle ALU.

__global__ __launch_bounds__(256, 6)
void brief_desc_kernel(const float* __restrict__ img,
                       const float* __restrict__ kp,
                       const float* __restrict__ ori,
                       const float* __restrict__ oy1v,
                       const float* __restrict__ ox1v,
                       const float* __restrict__ oy2v,
                       const float* __restrict__ ox2v,
                       const float* __restrict__ thr,
                       const int*   __restrict__ radii,
                       float* __restrict__ out)
{
    __shared__ float S[NR * PITCH];  // 16.3 KB linear SAT (60 rows)
    __shared__ float seg[64 * 5];    // column-scan segment totals, stride 5
    __shared__ float red[8];

    const int blk = blockIdx.x;      // b*K + k
    const int b   = blk >> 11;       // Kc = 2048
    const int tid = threadIdx.x;

    // --- minimal pre-phase state: patch origin only (keeps regs low in A/B) ---
    int iy, ix;
    {
        const float kpy = kp[blk * 2 + 0];
        const float kpx = kp[blk * 2 + 1];
        iy = (int)rintf(fminf(fmaxf(kpy, 0.0f), (float)(Hc - 1)));
        ix = (int)rintf(fminf(fmaxf(kpx, 0.0f), (float)(Wc - 1)));
    }
    const int oy0 = iy - 30;
    const int ox0 = (ix - 31) & ~3;  // 4-aligned for float4 LDG
    const float* imb = img + (size_t)b * Hc * Wc;

    // ===== Phase A: fused load + row prefix (coalesced float4 + shfl scan) =====
    {
        const int lane16 = tid & 15;          // chunk index within row
        const int grp    = tid >> 4;          // 16 row-groups; warp = 2 rows
        const int gxc    = ox0 + (lane16 << 2);
        const bool xok   = (gxc >= 0) & (gxc <= Wc - 4);  // chunks never straddle

        // passes 0..2: rows 0..47 (all warps); pass 3: rows 48..59 (warps 0..5)
        #pragma unroll
        for (int p = 0; p < 4; p++) {
            const int r = (p << 4) + grp;
            if (p == 3 && grp >= 12) break;   // whole-warp exit (warps 6,7)
            const int gy = oy0 + r;
            float4 e = make_float4(0.f, 0.f, 0.f, 0.f);
            if (xok && gy >= 0 && gy < Hc)
                e = *reinterpret_cast<const float4*>(imb + (size_t)gy * Wc + gxc);

            float v0 = e.x;
            float v1 = v0 + e.y;
            float v2 = v1 + e.z;
            float v3 = v2 + e.w;

            float t = v3;                     // inclusive scan of chunk totals
            #pragma unroll
            for (int d = 1; d < 16; d <<= 1) {
                const float n = __shfl_up_sync(0xffffffffu, t, d, 16);
                if (lane16 >= d) t += n;
            }
            const float off = t - v3;         // exclusive prefix for this chunk

            *reinterpret_cast<float4*>(&S[r * PITCH + (lane16 << 2)]) =
                make_float4(v0 + off, v1 + off, v2 + off, v3 + off);
        }
    }
    __syncthreads();

    // ===== Phase B: column prefix, parallel over 4 segments of 15 rows =====
    // v[15] register-buffered scan; linear stride-PITCH walk (immediate offsets).
    {
        const int c    = tid & 63;            // column
        const int q    = tid >> 6;            // row segment 0..3
        const int base = (q * 15) * PITCH + c;

        float v[15];
        float s = 0.0f;
        #pragma unroll
        for (int i = 0; i < 15; i++) {
            s += S[base + i * PITCH];
            v[i] = s;
        }
        seg[c * 5 + q] = s;
        __syncthreads();

        float off = 0.0f;
        #pragma unroll
        for (int qq = 0; qq < 3; qq++)
            if (qq < q) off += seg[c * 5 + qq];

        #pragma unroll
        for (int i = 0; i < 15; i++)
            S[base + i * PITCH] = v[i] + off;
    }
    __syncthreads();

    // ===== Phase C: deferred keypoint/pattern state + sampling =====
    const float kpy = kp[blk * 2 + 0];        // broadcast reload (L1-hit)
    const float kpx = kp[blk * 2 + 1];
    const float valid = (kpy >= 0.0f) ? 1.0f : 0.0f;
    const float y = fminf(fmaxf(kpy, 0.0f), (float)(Hc - 1));
    const float x = fminf(fmaxf(kpx, 0.0f), (float)(Wc - 1));

    const float theta = ori[(size_t)b * Hc * Wc + (size_t)iy * Wc + ix];
    float st, ct;
    __sincosf(theta, &st, &ct);               // |theta|<=pi: fast path, err ~2^-21

    const float o_y1 = oy1v[tid];
    const float o_x1 = ox1v[tid];
    const float o_y2 = oy2v[tid];
    const float o_x2 = ox2v[tid];
    const float th   = thr[tid];
    const int   rad  = radii[tid];
    const float dn   = (float)(2 * rad + 1);
    const float invden = __fdividef(1.0f, dn * dn);   // MUFU.RCP, err 2^-22

    const float p1y = y + (o_x1 * st + o_y1 * ct);
    const float p1x = x + (o_x1 * ct - o_y1 * st);
    const float p2y = y + (o_x2 * st + o_y2 * ct);
    const float p2x = x + (o_x2 * ct - o_y2 * st);

    auto boxavg = [&](float py, float px) -> float {
        // reference order: round first, then clip
        const float jyf = fminf(fmaxf(rintf(py), 0.0f), (float)(Hc - 1));
        const float jxf = fminf(fmaxf(rintf(px), 0.0f), (float)(Wc - 1));
        const int ly = (int)jyf - oy0;        // in [7,53]
        const int lx = (int)jxf - ox0;        // in [8,57]
        const int y1 = (ly - rad - 1) * PITCH, y2 = (ly + rad) * PITCH;
        const int x1 = lx - rad - 1,           x2 = lx + rad;
        const float s = S[y2 + x2] - S[y1 + x2] - S[y2 + x1] + S[y1 + x1];
        return s * invden;
    };

    const float d = boxavg(p1y, p1x) - boxavg(p2y, p2x) - th;

    // ===== Phase D: L2 normalize + write =====
    float sq = d * d;
    #pragma unroll
    for (int off = 16; off; off >>= 1)
        sq += __shfl_xor_sync(0xffffffffu, sq, off);
    if ((tid & 31) == 0) red[tid >> 5] = sq;
    __syncthreads();
    const float tot = red[0] + red[1] + red[2] + red[3]
                    + red[4] + red[5] + red[6] + red[7];
    const float norm  = sqrtf(tot);
    const float scale = valid / fmaxf(norm, 1e-12f);

    out[(size_t)blk * Pc + tid] = d * scale;
}

extern "C" void kernel_launch(void* const* d_in, const int* in_sizes, int n_in,
                              void* d_out, int out_size)
{
    const float* img  = (const float*)d_in[0];  // image (B,1,H,W)
    const float* kp   = (const float*)d_in[1];  // keypoints (B,K,2)
    const float* ori  = (const float*)d_in[2];  // orientation (B,1,H,W)
    const float* oy1  = (const float*)d_in[3];
    const float* ox1  = (const float*)d_in[4];
    const float* oy2  = (const float*)d_in[5];
    const float* ox2  = (const float*)d_in[6];
    const float* thr  = (const float*)d_in[7];
    const int*   rad  = (const int*)d_in[8];
    float* out = (float*)d_out;

    brief_desc_kernel<<<Bc * Kc, Pc>>>(img, kp, ori, oy1, ox1, oy2, ox2, thr, rad, out);
}